// round 13
// baseline (speedup 1.0000x reference)
#include <cuda_runtime.h>
#include <cuda_bf16.h>
#include <math.h>
#include <stdint.h>

// Problem constants
#define BB   16
#define NN1  1024
#define NN2  4096
#define CC1  256
#define CC2  128
#define CIN  384           // C1 + C2
#define HH   256           // H1 == H2
#define MM   (BB * NN2)    // 65536 rows through the MLP

// ---------------------------------------------------------------------------
// Scratch (device globals; no allocations allowed)
// ---------------------------------------------------------------------------
__device__ float g_f1t[(size_t)BB * NN1 * CC1];     // f1 transposed [B][N1][C1]
__device__ __align__(256) unsigned short g_Xh[(size_t)MM * CIN];  // X bf16 hi, row-major
__device__ __align__(256) unsigned short g_Xl[(size_t)MM * CIN];  // X bf16 lo
__device__ __align__(256) uint32_t g_Y1p[(size_t)HH * MM];  // layer1 pre-BN, packed bf16 pair, col-major
__device__ __align__(256) unsigned short g_Y1h[(size_t)MM * HH];  // act(Y1) bf16 hi, row-major
__device__ __align__(256) unsigned short g_Y1l[(size_t)MM * HH];  // act(Y1) bf16 lo
__device__ __align__(256) uint32_t g_Y2p[(size_t)HH * MM];  // layer2 pre-BN, packed bf16 pair, col-major
__device__ float g_sum[4 * HH];                     // [sum1 | sq1 | sum2 | sq2]
__device__ float g_nrm[4 * HH];                     // [sc1 | sh1 | sc2 | sh2]
__device__ __align__(256) unsigned short g_W1h[HH * CIN];
__device__ __align__(256) unsigned short g_W1l[HH * CIN];
__device__ __align__(256) unsigned short g_W2h[HH * HH];
__device__ __align__(256) unsigned short g_W2l[HH * HH];

// ---------------------------------------------------------------------------
// Helpers
// ---------------------------------------------------------------------------
__device__ __forceinline__ uint32_t smem_to_u32(const void* p) {
    uint32_t a;
    asm("{ .reg .u64 t; cvta.to.shared.u64 t, %1; cvt.u32.u64 %0, t; }" : "=r"(a) : "l"(p));
    return a;
}
__device__ __forceinline__ void bsplit(float x, unsigned short& h, unsigned short& l) {
    __nv_bfloat16 hb = __float2bfloat16_rn(x);
    float r = x - __bfloat162float(hb);
    __nv_bfloat16 lb = __float2bfloat16_rn(r);
    h = __bfloat16_as_ushort(hb);
    l = __bfloat16_as_ushort(lb);
}
__device__ __forceinline__ uint32_t packsplit(float x) {
    unsigned short h, l;
    bsplit(x, h, l);
    return (uint32_t)h | ((uint32_t)l << 16);
}
__device__ __forceinline__ float unpacksplit(uint32_t p) {
    float h = __bfloat162float(__ushort_as_bfloat16((unsigned short)(p & 0xFFFFu)));
    float l = __bfloat162float(__ushort_as_bfloat16((unsigned short)(p >> 16)));
    return h + l;
}
__device__ __forceinline__ void cpa16(uint32_t d, const void* s) {
    asm volatile("cp.async.cg.shared.global [%0], [%1], 16;" :: "r"(d), "l"(s));
}
__device__ __forceinline__ void cp_commit() {
    asm volatile("cp.async.commit_group;");
}
template <int N>
__device__ __forceinline__ void cp_wait() {
    asm volatile("cp.async.wait_group %0;" :: "n"(N));
}
// mma.sync m16n8k16 bf16 -> f32 (HMMA path on sm_103; sm_80+ PTX)
__device__ __forceinline__ void mma16816(float* c, const uint32_t* a, const uint32_t* b) {
    asm volatile(
        "mma.sync.aligned.m16n8k16.row.col.f32.bf16.bf16.f32 "
        "{%0,%1,%2,%3}, {%4,%5,%6,%7}, {%8,%9}, {%0,%1,%2,%3};"
        : "+f"(c[0]), "+f"(c[1]), "+f"(c[2]), "+f"(c[3])
        : "r"(a[0]), "r"(a[1]), "r"(a[2]), "r"(a[3]), "r"(b[0]), "r"(b[1]));
}
// ldmatrix x4 (sm_75+): four 8x8 b16 tiles, per-lane row addresses
__device__ __forceinline__ void ldm_x4(uint32_t* r, uint32_t addr) {
    asm volatile("ldmatrix.sync.aligned.m8n8.x4.shared.b16 {%0,%1,%2,%3}, [%4];"
                 : "=r"(r[0]), "=r"(r[1]), "=r"(r[2]), "=r"(r[3]) : "r"(addr));
}

// ---------------------------------------------------------------------------
// prep kernel: zero BN stats + split W1, W2 (fp32 -> bf16 hi/lo)
// ---------------------------------------------------------------------------
#define NW1 (HH * CIN)
#define NW2 (HH * HH)
__global__ void prep_w_kernel(const float* __restrict__ W1,
                              const float* __restrict__ W2) {
    const int i = blockIdx.x * 256 + threadIdx.x;
    if (blockIdx.x == 0 && threadIdx.x < 256) {
#pragma unroll
        for (int j = 0; j < 4; j++) g_sum[j * 256 + threadIdx.x] = 0.f;
    }
    if (i < NW1) {
        unsigned short h, l;
        bsplit(W1[i], h, l);
        g_W1h[i] = h; g_W1l[i] = l;
    } else if (i < NW1 + NW2) {
        const int k = i - NW1;
        unsigned short h, l;
        bsplit(W2[k], h, l);
        g_W2h[k] = h; g_W2l[k] = l;
    }
}

// ---------------------------------------------------------------------------
// Transpose features1 [B][C1][N1] -> g_f1t [B][N1][C1]  (fp32, for gather)
// ---------------------------------------------------------------------------
__global__ __launch_bounds__(256) void transpose_f1_kernel(const float* __restrict__ f1) {
    __shared__ float t[32][33];
    const int b = blockIdx.z, n0 = blockIdx.x * 32, c0 = blockIdx.y * 32;
    const int tx = threadIdx.x, ty = threadIdx.y;
    const float* src = f1 + (size_t)b * CC1 * NN1;
#pragma unroll
    for (int i = 0; i < 4; i++)
        t[ty + 8 * i][tx] = src[(size_t)(c0 + ty + 8 * i) * NN1 + n0 + tx];
    __syncthreads();
    float* dst = g_f1t + (size_t)b * NN1 * CC1;
#pragma unroll
    for (int i = 0; i < 4; i++)
        dst[(size_t)(n0 + ty + 8 * i) * CC1 + c0 + tx] = t[tx][ty + 8 * i];
}

// ---------------------------------------------------------------------------
// Transpose features2 [B][C2][N2] into X[:, C1:CIN], written bf16-split
// ---------------------------------------------------------------------------
__global__ __launch_bounds__(256) void concat_f2_kernel(const float* __restrict__ f2) {
    __shared__ float t[32][33];
    const int b = blockIdx.z, n0 = blockIdx.x * 32, c0 = blockIdx.y * 32;
    const int tx = threadIdx.x, ty = threadIdx.y;
    const float* src = f2 + (size_t)b * CC2 * NN2;
#pragma unroll
    for (int i = 0; i < 4; i++)
        t[ty + 8 * i][tx] = src[(size_t)(c0 + ty + 8 * i) * NN2 + n0 + tx];
    __syncthreads();
#pragma unroll
    for (int i = 0; i < 4; i++) {
        const size_t m = (size_t)b * NN2 + n0 + ty + 8 * i;
        unsigned short h, l;
        bsplit(t[tx][ty + 8 * i], h, l);
        g_Xh[m * CIN + CC1 + c0 + tx] = h;
        g_Xl[m * CIN + CC1 + c0 + tx] = l;
    }
}

// ---------------------------------------------------------------------------
// 3-NN + inverse-distance interpolation -> X[:, 0:C1] (bf16-split)
// 512 blocks (128 queries/block), 2 threads per query each scanning 512 refs,
// then a tie-stable 3-way merge (half 0 preferred on ties = lower index,
// matching top_k's stable order). Distance arithmetic bit-exact vs reference.
// ---------------------------------------------------------------------------
__global__ __launch_bounds__(256) void knn_interp_kernel(const float* __restrict__ p1,
                                                         const float* __restrict__ p2) {
    __shared__ float4 sp[NN1];
    __shared__ float  s_bd[2 * 128 * 3];
    __shared__ int    s_bi[2 * 128 * 3];
    __shared__ float  s_w[128 * 3];
    __shared__ int    s_idx[128 * 3];

    const int b    = blockIdx.y;
    const int tid  = threadIdx.x;
    const int ql   = tid & 127;
    const int half = tid >> 7;
    const int q0   = blockIdx.x * 128;

    const float* p1b = p1 + (size_t)b * 3 * NN1;
    for (int i = tid; i < NN1; i += 256) {
        float x = p1b[i], y = p1b[NN1 + i], z = p1b[2 * NN1 + i];
        float n = __fadd_rn(__fadd_rn(__fmul_rn(x, x), __fmul_rn(y, y)), __fmul_rn(z, z));
        sp[i] = make_float4(x, y, z, n);
    }
    __syncthreads();

    const int q = q0 + ql;
    const float* p2b = p2 + (size_t)b * 3 * NN2;
    const float qx = p2b[q], qy = p2b[NN2 + q], qz = p2b[2 * NN2 + q];
    const float qn = __fadd_rn(__fadd_rn(__fmul_rn(qx, qx), __fmul_rn(qy, qy)),
                               __fmul_rn(qz, qz));

    float d0 = 1e30f, d1 = 1e30f, d2 = 1e30f;
    int   i0 = 0, i1 = 0, i2 = 0;
    const int nbeg = half * 512;
#pragma unroll 4
    for (int n = nbeg; n < nbeg + 512; n++) {
        const float4 f = sp[n];
        const float dot = __fmaf_rn(qz, f.z, __fmaf_rn(qy, f.y, __fmul_rn(qx, f.x)));
        const float d = __fsub_rn(__fadd_rn(qn, f.w), __fadd_rn(dot, dot));
        if (d < d2) {
            if (d < d1) {
                d2 = d1; i2 = i1;
                if (d < d0) { d1 = d0; i1 = i0; d0 = d; i0 = n; }
                else        { d1 = d;  i1 = n; }
            } else { d2 = d; i2 = n; }
        }
    }
    const int base = (half * 128 + ql) * 3;
    s_bd[base + 0] = d0; s_bd[base + 1] = d1; s_bd[base + 2] = d2;
    s_bi[base + 0] = i0; s_bi[base + 1] = i1; s_bi[base + 2] = i2;
    __syncthreads();

    if (tid < 128) {
        const float* da = &s_bd[tid * 3];
        const int*   ia = &s_bi[tid * 3];
        const float* db = &s_bd[(128 + tid) * 3];
        const int*   ib = &s_bi[(128 + tid) * 3];
        float dm[3]; int im[3];
        int ai = 0, bi = 0;
#pragma unroll
        for (int s = 0; s < 3; s++) {
            const float dA = da[ai], dB = db[bi];
            if (dB < dA) { dm[s] = dB; im[s] = ib[bi]; bi++; }
            else         { dm[s] = dA; im[s] = ia[ai]; ai++; }
        }
        const float v0 = __fdiv_rn(1.f, fmaxf(dm[0], 1e-10f));
        const float v1 = __fdiv_rn(1.f, fmaxf(dm[1], 1e-10f));
        const float v2 = __fdiv_rn(1.f, fmaxf(dm[2], 1e-10f));
        const float s  = __fadd_rn(__fadd_rn(v0, v1), v2);
        s_idx[tid * 3 + 0] = im[0]; s_idx[tid * 3 + 1] = im[1]; s_idx[tid * 3 + 2] = im[2];
        s_w[tid * 3 + 0] = __fdiv_rn(v0, s);
        s_w[tid * 3 + 1] = __fdiv_rn(v1, s);
        s_w[tid * 3 + 2] = __fdiv_rn(v2, s);
    }
    __syncthreads();

    const float* f1t = g_f1t + (size_t)b * NN1 * CC1;
    const size_t mrow0 = (size_t)b * NN2 + q0;
    const int c = tid;
    for (int qq = 0; qq < 128; qq++) {
        const int   a0 = s_idx[qq * 3 + 0], a1 = s_idx[qq * 3 + 1], a2 = s_idx[qq * 3 + 2];
        const float w0 = s_w[qq * 3 + 0],  w1 = s_w[qq * 3 + 1],  w2 = s_w[qq * 3 + 2];
        const float t0 = __fmul_rn(f1t[(size_t)a0 * CC1 + c], w0);
        const float t1 = __fmul_rn(f1t[(size_t)a1 * CC1 + c], w1);
        const float t2 = __fmul_rn(f1t[(size_t)a2 * CC1 + c], w2);
        const float v  = __fadd_rn(__fadd_rn(t0, t1), t2);
        unsigned short h, l;
        bsplit(v, h, l);
        g_Xh[(mrow0 + qq) * CIN + c] = h;
        g_Xl[(mrow0 + qq) * CIN + c] = l;
    }
}

// ---------------------------------------------------------------------------
// mma.sync bf16-split GEMM: Y[c][m] = A[m,:] . W[c,:] + bias[c]
// A and W pre-split (bf16 hi/lo) row-major. cp.async double-buffered
// (2 stages x 4 tiles). ldmatrix.x4 fragment loads. 3-term compensation:
// ah*bh + al*bh + ah*bl (fp32 accumulators).
// Block = 128 rows x 128 cols, 8 warps (2M x 4N), 64x32 per warp.
// Grid (2, 512): n-tile fastest so A panels are L2-resident on reuse.
// Epilogue: stage tile in smem F[n][132] -> warp-per-column stores of
// PACKED bf16-pair uint4 (halves Y traffic) + BN stats via shfl.
// ---------------------------------------------------------------------------
#define ASTRIDE 40                    // u16 stride per row (32 k + 8 pad)
#define TILE_U16 (128 * ASTRIDE)      // 5120 u16 = 10240 B
#define STAGE_U16 (4 * TILE_U16)      // 20480 u16 = 40960 B
#define GEMM_SMEM (2 * STAGE_U16 * 2 + 3 * 128 * 4)   // 83456 B

template <int K>
__global__ __launch_bounds__(256)
void gemm_mma_kernel(const unsigned short* __restrict__ GAh,
                     const unsigned short* __restrict__ GAl,
                     const unsigned short* __restrict__ GWh,
                     const unsigned short* __restrict__ GWl,
                     const float* __restrict__ bias,
                     uint32_t* __restrict__ Yp,
                     float* __restrict__ osum,
                     float* __restrict__ osq) {
    extern __shared__ char smem[];
    const uint32_t sb = smem_to_u32(smem);
    float* s_bias = (float*)(smem + 2 * STAGE_U16 * 2);
    float* s_sum  = s_bias + 128;
    float* s_sq   = s_sum + 128;

    const int tid  = threadIdx.x;
    const int lane = tid & 31;
    const int wid  = tid >> 5;
    const int n0   = blockIdx.x * 128;
    const int m0   = blockIdx.y * 128;
    const int m_base = (wid & 1) * 64;
    const int n_base = (wid >> 1) * 32;

    if (tid < 128) s_bias[tid] = bias[n0 + tid];

    float acc[4][4][4];
#pragma unroll
    for (int a = 0; a < 4; a++)
#pragma unroll
        for (int b = 0; b < 4; b++)
#pragma unroll
            for (int c = 0; c < 4; c++) acc[a][b][c] = 0.f;

    // cp.async mapping: each thread copies 2x16B per tile (rows tid>>1)
    const int crow = tid >> 1;
    const int ckoff = (tid & 1) * 16;                    // u16 offset within 32-k chunk

    auto issue = [&](int ch, int st) {
        const int kb = ch * 32 + ckoff;
        const unsigned short* a_h = GAh + (size_t)(m0 + crow) * K + kb;
        const unsigned short* a_l = GAl + (size_t)(m0 + crow) * K + kb;
        const unsigned short* w_h = GWh + (size_t)(n0 + crow) * K + kb;
        const unsigned short* w_l = GWl + (size_t)(n0 + crow) * K + kb;
        const uint32_t so = sb + (uint32_t)(st * STAGE_U16 + crow * ASTRIDE + ckoff) * 2u;
        cpa16(so, a_h);                          cpa16(so + 16, a_h + 8);
        cpa16(so + TILE_U16 * 2, a_l);           cpa16(so + TILE_U16 * 2 + 16, a_l + 8);
        cpa16(so + TILE_U16 * 4, w_h);           cpa16(so + TILE_U16 * 4 + 16, w_h + 8);
        cpa16(so + TILE_U16 * 6, w_l);           cpa16(so + TILE_U16 * 6 + 16, w_l + 8);
        cp_commit();
    };

    // ldmatrix per-lane offsets (u16 units within a tile)
    const uint32_t a_loff = (uint32_t)(((lane & 7) + ((lane >> 3) & 1) * 8) * ASTRIDE
                                       + (lane >> 4) * 8);
    const uint32_t b_loff = (uint32_t)(((lane & 7) + (lane >> 4) * 8) * ASTRIDE
                                       + ((lane >> 3) & 1) * 8);

    constexpr int NCH = K / 32;
    issue(0, 0);
    int buf = 0;
    for (int ch = 0; ch < NCH; ch++) {
        if (ch + 1 < NCH) { issue(ch + 1, buf ^ 1); cp_wait<1>(); }
        else              { cp_wait<0>(); }
        __syncthreads();

        const uint32_t sAh = sb + (uint32_t)(buf * STAGE_U16) * 2u;
        const uint32_t sAl = sAh + TILE_U16 * 2u;
        const uint32_t sWh = sAl + TILE_U16 * 2u;
        const uint32_t sWl = sWh + TILE_U16 * 2u;

#pragma unroll
        for (int kk = 0; kk < 32; kk += 16) {
            uint32_t afh[4][4], afl[4][4];
#pragma unroll
            for (int mt = 0; mt < 4; mt++) {
                const uint32_t off = ((uint32_t)((m_base + mt * 16) * ASTRIDE + kk)
                                      + a_loff) * 2u;
                ldm_x4(afh[mt], sAh + off);
                ldm_x4(afl[mt], sAl + off);
            }
            uint32_t bfh[4][2], bfl[4][2];
#pragma unroll
            for (int np = 0; np < 2; np++) {
                const uint32_t off = ((uint32_t)((n_base + np * 16) * ASTRIDE + kk)
                                      + b_loff) * 2u;
                uint32_t th[4], tl[4];
                ldm_x4(th, sWh + off);
                ldm_x4(tl, sWl + off);
                bfh[2 * np][0] = th[0]; bfh[2 * np][1] = th[1];
                bfh[2 * np + 1][0] = th[2]; bfh[2 * np + 1][1] = th[3];
                bfl[2 * np][0] = tl[0]; bfl[2 * np][1] = tl[1];
                bfl[2 * np + 1][0] = tl[2]; bfl[2 * np + 1][1] = tl[3];
            }
#pragma unroll
            for (int mt = 0; mt < 4; mt++)
#pragma unroll
                for (int nt = 0; nt < 4; nt++) {
                    mma16816(acc[mt][nt], afh[mt], bfh[nt]);
                    mma16816(acc[mt][nt], afl[mt], bfh[nt]);
                    mma16816(acc[mt][nt], afh[mt], bfl[nt]);
                }
        }
        __syncthreads();
        buf ^= 1;
    }

    // ---- Epilogue: stage into F[n][132], packed-pair col stores + BN stats ----
    float* F = (float*)smem;            // 128*132*4 = 67584 B, fits in stage area
#pragma unroll
    for (int nt = 0; nt < 4; nt++) {
        const int n = n_base + nt * 8 + 2 * (lane & 3);
        const float b0 = s_bias[n], b1 = s_bias[n + 1];
#pragma unroll
        for (int mt = 0; mt < 4; mt++) {
            const int r = m_base + mt * 16 + (lane >> 2);
            F[n * 132 + r]           = acc[mt][nt][0] + b0;
            F[(n + 1) * 132 + r]     = acc[mt][nt][1] + b1;
            F[n * 132 + r + 8]       = acc[mt][nt][2] + b0;
            F[(n + 1) * 132 + r + 8] = acc[mt][nt][3] + b1;
        }
    }
    __syncthreads();
#pragma unroll 1
    for (int c = wid; c < 128; c += 8) {
        float4 v = *(float4*)&F[c * 132 + lane * 4];
        float s = v.x + v.y + v.z + v.w;
        float q = v.x * v.x + v.y * v.y + v.z * v.z + v.w * v.w;
#pragma unroll
        for (int off = 16; off >= 1; off >>= 1) {
            s += __shfl_xor_sync(0xFFFFFFFFu, s, off);
            q += __shfl_xor_sync(0xFFFFFFFFu, q, off);
        }
        uint4 pk;
        pk.x = packsplit(v.x); pk.y = packsplit(v.y);
        pk.z = packsplit(v.z); pk.w = packsplit(v.w);
        *(uint4*)&Yp[(size_t)(n0 + c) * MM + m0 + lane * 4] = pk;
        if (lane == 0) { s_sum[c] = s; s_sq[c] = q; }
    }
    __syncthreads();
    if (tid < 128) {
        atomicAdd(&osum[n0 + tid], s_sum[tid]);
        atomicAdd(&osq[n0 + tid], s_sq[tid]);
    }
}

// ---------------------------------------------------------------------------
// Finalize BN stats -> per-channel (scale, shift)
// ---------------------------------------------------------------------------
__global__ void stats_final_kernel(const float* __restrict__ gamma,
                                   const float* __restrict__ beta,
                                   int layer) {
    const int c = threadIdx.x;
    if (c >= HH) return;
    const float invM = 1.f / (float)MM;
    const float s = g_sum[layer * 512 + c];
    const float q = g_sum[layer * 512 + 256 + c];
    const float mean = s * invM;
    const float var = fmaxf(q * invM - mean * mean, 0.f);
    const float rstd = rsqrtf(var + 1e-3f);
    const float scale = gamma[c] * rstd;
    g_nrm[layer * 512 + c] = scale;
    g_nrm[layer * 512 + 256 + c] = beta[c] - mean * scale;
}

// ---------------------------------------------------------------------------
// prep2: Y1 packed-pair col-major -> BN+ReLU -> bf16 split, transposed to
// row-major [m][HH]. grid (MM/32, HH/32), block (32, 8); both sides coalesced.
// ---------------------------------------------------------------------------
__global__ __launch_bounds__(256) void prep2_kernel() {
    __shared__ float t[32][33];
    const int m0 = blockIdx.x * 32, c0 = blockIdx.y * 32;
    const int tx = threadIdx.x, ty = threadIdx.y;
#pragma unroll
    for (int i = 0; i < 4; i++) {
        const int cc = c0 + ty + 8 * i;
        float v = unpacksplit(g_Y1p[(size_t)cc * MM + m0 + tx]);
        t[ty + 8 * i][tx] = fmaxf(0.f, fmaf(v, g_nrm[cc], g_nrm[256 + cc]));
    }
    __syncthreads();
#pragma unroll
    for (int i = 0; i < 4; i++) {
        const size_t m = (size_t)(m0 + ty + 8 * i);
        unsigned short h, l;
        bsplit(t[tx][ty + 8 * i], h, l);
        g_Y1h[m * HH + c0 + tx] = h;
        g_Y1l[m * HH + c0 + tx] = l;
    }
}

// ---------------------------------------------------------------------------
// Final: layer-2 BN + ReLU, Y2 packed-pair col-major -> out[b][c][n]
// uint4 reads, float4 writes; grid (MM/1024, HH).
// ---------------------------------------------------------------------------
__global__ __launch_bounds__(256) void out_bn_kernel(float* __restrict__ out) {
    const int m = (blockIdx.x * 256 + threadIdx.x) * 4;
    const int c = blockIdx.y;
    uint4 p = *(const uint4*)&g_Y2p[(size_t)c * MM + m];
    const float sc = g_nrm[512 + c], sh = g_nrm[768 + c];
    float4 v;
    v.x = fmaxf(0.f, fmaf(unpacksplit(p.x), sc, sh));
    v.y = fmaxf(0.f, fmaf(unpacksplit(p.y), sc, sh));
    v.z = fmaxf(0.f, fmaf(unpacksplit(p.z), sc, sh));
    v.w = fmaxf(0.f, fmaf(unpacksplit(p.w), sc, sh));
    const int b = m >> 12;
    const int n = m & 4095;
    *(float4*)&out[(size_t)b * HH * NN2 + (size_t)c * NN2 + n] = v;
}

// ---------------------------------------------------------------------------
// Launch
// ---------------------------------------------------------------------------
extern "C" void kernel_launch(void* const* d_in, const int* in_sizes, int n_in,
                              void* d_out, int out_size) {
    (void)in_sizes; (void)n_in; (void)out_size;
    const float* points1   = (const float*)d_in[0];
    const float* points2   = (const float*)d_in[1];
    const float* features1 = (const float*)d_in[2];
    const float* features2 = (const float*)d_in[3];
    const float* W1  = (const float*)d_in[4];
    const float* b1  = (const float*)d_in[5];
    const float* gm1 = (const float*)d_in[6];
    const float* be1 = (const float*)d_in[7];
    const float* W2  = (const float*)d_in[8];
    const float* b2  = (const float*)d_in[9];
    const float* gm2 = (const float*)d_in[10];
    const float* be2 = (const float*)d_in[11];
    float* out = (float*)d_out;

    unsigned short *w1h, *w1l, *w2h, *w2l, *xh, *xl, *y1h, *y1l;
    uint32_t *y1p, *y2p;
    float *gsum;
    cudaGetSymbolAddress((void**)&w1h, g_W1h);
    cudaGetSymbolAddress((void**)&w1l, g_W1l);
    cudaGetSymbolAddress((void**)&w2h, g_W2h);
    cudaGetSymbolAddress((void**)&w2l, g_W2l);
    cudaGetSymbolAddress((void**)&xh,  g_Xh);
    cudaGetSymbolAddress((void**)&xl,  g_Xl);
    cudaGetSymbolAddress((void**)&y1h, g_Y1h);
    cudaGetSymbolAddress((void**)&y1l, g_Y1l);
    cudaGetSymbolAddress((void**)&y1p, g_Y1p);
    cudaGetSymbolAddress((void**)&y2p, g_Y2p);
    cudaGetSymbolAddress((void**)&gsum, g_sum);

    cudaFuncSetAttribute(gemm_mma_kernel<CIN>,
                         cudaFuncAttributeMaxDynamicSharedMemorySize, GEMM_SMEM);
    cudaFuncSetAttribute(gemm_mma_kernel<HH>,
                         cudaFuncAttributeMaxDynamicSharedMemorySize, GEMM_SMEM);

    prep_w_kernel<<<(NW1 + NW2 + 255) / 256, 256>>>(W1, W2);
    transpose_f1_kernel<<<dim3(NN1 / 32, CC1 / 32, BB), dim3(32, 8)>>>(features1);
    concat_f2_kernel<<<dim3(NN2 / 32, CC2 / 32, BB), dim3(32, 8)>>>(features2);
    knn_interp_kernel<<<dim3(NN2 / 128, BB), 256>>>(points1, points2);

    gemm_mma_kernel<CIN><<<dim3(2, MM / 128), 256, GEMM_SMEM>>>(
        xh, xl, w1h, w1l, b1, y1p, gsum, gsum + 256);
    stats_final_kernel<<<1, 256>>>(gm1, be1, 0);
    prep2_kernel<<<dim3(MM / 32, HH / 32), dim3(32, 8)>>>();

    gemm_mma_kernel<HH><<<dim3(2, MM / 128), 256, GEMM_SMEM>>>(
        y1h, y1l, w2h, w2l, b2, y2p, gsum + 512, gsum + 768);
    stats_final_kernel<<<1, 256>>>(gm2, be2, 1);

    out_bn_kernel<<<dim3(MM / 1024, HH), 256>>>(out);
}

// round 14
// speedup vs baseline: 1.0705x; 1.0705x over previous
#include <cuda_runtime.h>
#include <cuda_bf16.h>
#include <math.h>
#include <stdint.h>

// Problem constants
#define BB   16
#define NN1  1024
#define NN2  4096
#define CC1  256
#define CC2  128
#define CIN  384           // C1 + C2
#define HH   256           // H1 == H2
#define MM   (BB * NN2)    // 65536 rows through the MLP

// ---------------------------------------------------------------------------
// Scratch (device globals; no allocations allowed)
// ---------------------------------------------------------------------------
__device__ float g_f1t[(size_t)BB * NN1 * CC1];     // f1 transposed [B][N1][C1]
__device__ __align__(256) unsigned short g_Xh[(size_t)MM * CIN];  // X bf16 hi, row-major
__device__ __align__(256) unsigned short g_Xl[(size_t)MM * CIN];  // X bf16 lo
__device__ float g_Y1 [(size_t)HH * MM];            // layer1 pre-BN, COLUMN-major [c][m]
__device__ __align__(256) unsigned short g_Y1h[(size_t)MM * HH];  // act(Y1) bf16 hi, row-major
__device__ __align__(256) unsigned short g_Y1l[(size_t)MM * HH];  // act(Y1) bf16 lo
__device__ float g_Y2 [(size_t)HH * MM];            // layer2 pre-BN, COLUMN-major [c][m]
__device__ float g_sum[4 * HH];                     // [sum1 | sq1 | sum2 | sq2]
__device__ float g_nrm[4 * HH];                     // [sc1 | sh1 | sc2 | sh2]
__device__ __align__(256) unsigned short g_W1h[HH * CIN];
__device__ __align__(256) unsigned short g_W1l[HH * CIN];
__device__ __align__(256) unsigned short g_W2h[HH * HH];
__device__ __align__(256) unsigned short g_W2l[HH * HH];
__device__ int   g_knni[(size_t)MM * 3];            // top-3 neighbor indices
__device__ float g_knnw[(size_t)MM * 3];            // top-3 weights

// ---------------------------------------------------------------------------
// Helpers
// ---------------------------------------------------------------------------
__device__ __forceinline__ uint32_t smem_to_u32(const void* p) {
    uint32_t a;
    asm("{ .reg .u64 t; cvta.to.shared.u64 t, %1; cvt.u32.u64 %0, t; }" : "=r"(a) : "l"(p));
    return a;
}
__device__ __forceinline__ void bsplit(float x, unsigned short& h, unsigned short& l) {
    __nv_bfloat16 hb = __float2bfloat16_rn(x);
    float r = x - __bfloat162float(hb);
    __nv_bfloat16 lb = __float2bfloat16_rn(r);
    h = __bfloat16_as_ushort(hb);
    l = __bfloat16_as_ushort(lb);
}
__device__ __forceinline__ void cpa16(uint32_t d, const void* s) {
    asm volatile("cp.async.cg.shared.global [%0], [%1], 16;" :: "r"(d), "l"(s));
}
__device__ __forceinline__ void cp_commit() {
    asm volatile("cp.async.commit_group;");
}
template <int N>
__device__ __forceinline__ void cp_wait() {
    asm volatile("cp.async.wait_group %0;" :: "n"(N));
}
// mma.sync m16n8k16 bf16 -> f32 (HMMA path on sm_103; sm_80+ PTX)
__device__ __forceinline__ void mma16816(float* c, const uint32_t* a, const uint32_t* b) {
    asm volatile(
        "mma.sync.aligned.m16n8k16.row.col.f32.bf16.bf16.f32 "
        "{%0,%1,%2,%3}, {%4,%5,%6,%7}, {%8,%9}, {%0,%1,%2,%3};"
        : "+f"(c[0]), "+f"(c[1]), "+f"(c[2]), "+f"(c[3])
        : "r"(a[0]), "r"(a[1]), "r"(a[2]), "r"(a[3]), "r"(b[0]), "r"(b[1]));
}
// ldmatrix x4 (sm_75+): four 8x8 b16 tiles, per-lane row addresses
__device__ __forceinline__ void ldm_x4(uint32_t* r, uint32_t addr) {
    asm volatile("ldmatrix.sync.aligned.m8n8.x4.shared.b16 {%0,%1,%2,%3}, [%4];"
                 : "=r"(r[0]), "=r"(r[1]), "=r"(r[2]), "=r"(r[3]) : "r"(addr));
}

// ---------------------------------------------------------------------------
// prep kernel: zero BN stats + split W1, W2 (fp32 -> bf16 hi/lo)
// ---------------------------------------------------------------------------
#define NW1 (HH * CIN)
#define NW2 (HH * HH)
__global__ void prep_w_kernel(const float* __restrict__ W1,
                              const float* __restrict__ W2) {
    const int i = blockIdx.x * 256 + threadIdx.x;
    if (blockIdx.x == 0 && threadIdx.x < 256) {
#pragma unroll
        for (int j = 0; j < 4; j++) g_sum[j * 256 + threadIdx.x] = 0.f;
    }
    if (i < NW1) {
        unsigned short h, l;
        bsplit(W1[i], h, l);
        g_W1h[i] = h; g_W1l[i] = l;
    } else if (i < NW1 + NW2) {
        const int k = i - NW1;
        unsigned short h, l;
        bsplit(W2[k], h, l);
        g_W2h[k] = h; g_W2l[k] = l;
    }
}

// ---------------------------------------------------------------------------
// Transpose features1 [B][C1][N1] -> g_f1t [B][N1][C1]  (fp32, for gather)
// ---------------------------------------------------------------------------
__global__ __launch_bounds__(256) void transpose_f1_kernel(const float* __restrict__ f1) {
    __shared__ float t[32][33];
    const int b = blockIdx.z, n0 = blockIdx.x * 32, c0 = blockIdx.y * 32;
    const int tx = threadIdx.x, ty = threadIdx.y;
    const float* src = f1 + (size_t)b * CC1 * NN1;
#pragma unroll
    for (int i = 0; i < 4; i++)
        t[ty + 8 * i][tx] = src[(size_t)(c0 + ty + 8 * i) * NN1 + n0 + tx];
    __syncthreads();
    float* dst = g_f1t + (size_t)b * NN1 * CC1;
#pragma unroll
    for (int i = 0; i < 4; i++)
        dst[(size_t)(n0 + ty + 8 * i) * CC1 + c0 + tx] = t[tx][ty + 8 * i];
}

// ---------------------------------------------------------------------------
// Transpose features2 [B][C2][N2] into X[:, C1:CIN], written bf16-split
// ---------------------------------------------------------------------------
__global__ __launch_bounds__(256) void concat_f2_kernel(const float* __restrict__ f2) {
    __shared__ float t[32][33];
    const int b = blockIdx.z, n0 = blockIdx.x * 32, c0 = blockIdx.y * 32;
    const int tx = threadIdx.x, ty = threadIdx.y;
    const float* src = f2 + (size_t)b * CC2 * NN2;
#pragma unroll
    for (int i = 0; i < 4; i++)
        t[ty + 8 * i][tx] = src[(size_t)(c0 + ty + 8 * i) * NN2 + n0 + tx];
    __syncthreads();
#pragma unroll
    for (int i = 0; i < 4; i++) {
        const size_t m = (size_t)b * NN2 + n0 + ty + 8 * i;
        unsigned short h, l;
        bsplit(t[tx][ty + 8 * i], h, l);
        g_Xh[m * CIN + CC1 + c0 + tx] = h;
        g_Xl[m * CIN + CC1 + c0 + tx] = l;
    }
}

// ---------------------------------------------------------------------------
// kNN scan: top-3 by squared distance -> g_knni / g_knnw.
// 1024 blocks x 64 queries; 4 threads/query, each scanning 256 refs, then a
// tie-stable 4-way merge (lowest quarter preferred on equal d = lower index,
// matching top_k's stable order; per-quarter lists are (d, idx)-ascending).
// Distance arithmetic bit-exact vs reference (un-contracted intrinsics).
// ---------------------------------------------------------------------------
__global__ __launch_bounds__(256) void knn_scan_kernel(const float* __restrict__ p1,
                                                       const float* __restrict__ p2) {
    __shared__ float4 sp[NN1];
    __shared__ float  s_bd[4 * 64 * 3];
    __shared__ int    s_bi[4 * 64 * 3];

    const int b    = blockIdx.y;
    const int tid  = threadIdx.x;
    const int ql   = tid & 63;
    const int quad = tid >> 6;
    const int q0   = blockIdx.x * 64;

    const float* p1b = p1 + (size_t)b * 3 * NN1;
    for (int i = tid; i < NN1; i += 256) {
        float x = p1b[i], y = p1b[NN1 + i], z = p1b[2 * NN1 + i];
        float n = __fadd_rn(__fadd_rn(__fmul_rn(x, x), __fmul_rn(y, y)), __fmul_rn(z, z));
        sp[i] = make_float4(x, y, z, n);
    }
    __syncthreads();

    const int q = q0 + ql;
    const float* p2b = p2 + (size_t)b * 3 * NN2;
    const float qx = p2b[q], qy = p2b[NN2 + q], qz = p2b[2 * NN2 + q];
    const float qn = __fadd_rn(__fadd_rn(__fmul_rn(qx, qx), __fmul_rn(qy, qy)),
                               __fmul_rn(qz, qz));

    float d0 = 1e30f, d1 = 1e30f, d2 = 1e30f;
    int   i0 = 0, i1 = 0, i2 = 0;
    const int nbeg = quad * 256;
#pragma unroll 4
    for (int n = nbeg; n < nbeg + 256; n++) {
        const float4 f = sp[n];
        const float dot = __fmaf_rn(qz, f.z, __fmaf_rn(qy, f.y, __fmul_rn(qx, f.x)));
        const float d = __fsub_rn(__fadd_rn(qn, f.w), __fadd_rn(dot, dot));
        if (d < d2) {
            if (d < d1) {
                d2 = d1; i2 = i1;
                if (d < d0) { d1 = d0; i1 = i0; d0 = d; i0 = n; }
                else        { d1 = d;  i1 = n; }
            } else { d2 = d; i2 = n; }
        }
    }
    const int base = (quad * 64 + ql) * 3;
    s_bd[base + 0] = d0; s_bd[base + 1] = d1; s_bd[base + 2] = d2;
    s_bi[base + 0] = i0; s_bi[base + 1] = i1; s_bi[base + 2] = i2;
    __syncthreads();

    if (tid < 64) {
        int heads[4] = {0, 0, 0, 0};
        float dm[3]; int im[3];
#pragma unroll
        for (int s = 0; s < 3; s++) {
            int   bq = 0;
            float bd = s_bd[(0 * 64 + tid) * 3 + heads[0]];
#pragma unroll
            for (int qd = 1; qd < 4; qd++) {
                const float dd = s_bd[(qd * 64 + tid) * 3 + heads[qd]];
                if (dd < bd) { bd = dd; bq = qd; }      // strict <: lower quarter wins ties
            }
            dm[s] = bd;
            im[s] = s_bi[(bq * 64 + tid) * 3 + heads[bq]];
            heads[bq]++;
        }
        const float v0 = __fdiv_rn(1.f, fmaxf(dm[0], 1e-10f));
        const float v1 = __fdiv_rn(1.f, fmaxf(dm[1], 1e-10f));
        const float v2 = __fdiv_rn(1.f, fmaxf(dm[2], 1e-10f));
        const float s  = __fadd_rn(__fadd_rn(v0, v1), v2);
        const size_t m = (size_t)b * NN2 + q0 + tid;
        g_knni[m * 3 + 0] = im[0];
        g_knni[m * 3 + 1] = im[1];
        g_knni[m * 3 + 2] = im[2];
        g_knnw[m * 3 + 0] = __fdiv_rn(v0, s);
        g_knnw[m * 3 + 1] = __fdiv_rn(v1, s);
        g_knnw[m * 3 + 2] = __fdiv_rn(v2, s);
    }
}

// ---------------------------------------------------------------------------
// kNN gather: X[:, 0:C1] = weighted 3-row gather of f1t (relaxed math — only
// the SELECTION needed bit-exactness; value rounding ~1e-7 is far below the
// 8e-6 bf16-split floor). 1024 blocks x 64 queries, thread = channel.
// f1t (16 MB) is L2-resident -> deep-MLP L2-latency hidden.
// ---------------------------------------------------------------------------
__global__ __launch_bounds__(256) void knn_gather_kernel() {
    __shared__ int   s_i[64 * 3];
    __shared__ float s_w[64 * 3];
    const int blk = blockIdx.x;
    const int b   = blk >> 6;            // 64 blocks per batch
    const int q0  = (blk & 63) * 64;
    const int tid = threadIdx.x;
    const size_t m0 = (size_t)b * NN2 + q0;

    if (tid < 192) {
        s_i[tid] = g_knni[m0 * 3 + tid];
        s_w[tid] = g_knnw[m0 * 3 + tid];
    }
    __syncthreads();

    const float* f1t = g_f1t + (size_t)b * NN1 * CC1;
    const int c = tid;
#pragma unroll 2
    for (int qq = 0; qq < 64; qq++) {
        const int   a0 = s_i[qq * 3 + 0], a1 = s_i[qq * 3 + 1], a2 = s_i[qq * 3 + 2];
        const float w0 = s_w[qq * 3 + 0], w1 = s_w[qq * 3 + 1], w2 = s_w[qq * 3 + 2];
        const float v = fmaf(w2, __ldg(&f1t[(size_t)a2 * CC1 + c]),
                        fmaf(w1, __ldg(&f1t[(size_t)a1 * CC1 + c]),
                             w0 * __ldg(&f1t[(size_t)a0 * CC1 + c])));
        unsigned short h, l;
        bsplit(v, h, l);
        g_Xh[(m0 + qq) * CIN + c] = h;
        g_Xl[(m0 + qq) * CIN + c] = l;
    }
}

// ---------------------------------------------------------------------------
// mma.sync bf16-split GEMM: Y[c][m] = A[m,:] . W[c,:] + bias[c]
// A and W pre-split (bf16 hi/lo) row-major. cp.async double-buffered
// (2 stages x 4 tiles). ldmatrix.x4 fragment loads. 3-term compensation:
// ah*bh + al*bh + ah*bl (fp32 accumulators).
// Block = 128 rows x 128 cols, 8 warps (2M x 4N), 64x32 per warp.
// Grid (2, 512): n-tile fastest so A panels are L2-resident on reuse.
// Epilogue: stage tile in smem F[n][132] -> warp-per-column float4 stores
// (fully coalesced, fp32) + BN stats via shfl.
// ---------------------------------------------------------------------------
#define ASTRIDE 40                    // u16 stride per row (32 k + 8 pad)
#define TILE_U16 (128 * ASTRIDE)      // 5120 u16 = 10240 B
#define STAGE_U16 (4 * TILE_U16)      // 20480 u16 = 40960 B
#define GEMM_SMEM (2 * STAGE_U16 * 2 + 3 * 128 * 4)   // 83456 B

template <int K>
__global__ __launch_bounds__(256)
void gemm_mma_kernel(const unsigned short* __restrict__ GAh,
                     const unsigned short* __restrict__ GAl,
                     const unsigned short* __restrict__ GWh,
                     const unsigned short* __restrict__ GWl,
                     const float* __restrict__ bias,
                     float* __restrict__ Y,
                     float* __restrict__ osum,
                     float* __restrict__ osq) {
    extern __shared__ char smem[];
    const uint32_t sb = smem_to_u32(smem);
    float* s_bias = (float*)(smem + 2 * STAGE_U16 * 2);
    float* s_sum  = s_bias + 128;
    float* s_sq   = s_sum + 128;

    const int tid  = threadIdx.x;
    const int lane = tid & 31;
    const int wid  = tid >> 5;
    const int n0   = blockIdx.x * 128;
    const int m0   = blockIdx.y * 128;
    const int m_base = (wid & 1) * 64;
    const int n_base = (wid >> 1) * 32;

    if (tid < 128) s_bias[tid] = bias[n0 + tid];

    float acc[4][4][4];
#pragma unroll
    for (int a = 0; a < 4; a++)
#pragma unroll
        for (int b = 0; b < 4; b++)
#pragma unroll
            for (int c = 0; c < 4; c++) acc[a][b][c] = 0.f;

    // cp.async mapping: each thread copies 2x16B per tile (rows tid>>1)
    const int crow = tid >> 1;
    const int ckoff = (tid & 1) * 16;                    // u16 offset within 32-k chunk

    auto issue = [&](int ch, int st) {
        const int kb = ch * 32 + ckoff;
        const unsigned short* a_h = GAh + (size_t)(m0 + crow) * K + kb;
        const unsigned short* a_l = GAl + (size_t)(m0 + crow) * K + kb;
        const unsigned short* w_h = GWh + (size_t)(n0 + crow) * K + kb;
        const unsigned short* w_l = GWl + (size_t)(n0 + crow) * K + kb;
        const uint32_t so = sb + (uint32_t)(st * STAGE_U16 + crow * ASTRIDE + ckoff) * 2u;
        cpa16(so, a_h);                          cpa16(so + 16, a_h + 8);
        cpa16(so + TILE_U16 * 2, a_l);           cpa16(so + TILE_U16 * 2 + 16, a_l + 8);
        cpa16(so + TILE_U16 * 4, w_h);           cpa16(so + TILE_U16 * 4 + 16, w_h + 8);
        cpa16(so + TILE_U16 * 6, w_l);           cpa16(so + TILE_U16 * 6 + 16, w_l + 8);
        cp_commit();
    };

    // ldmatrix per-lane offsets (u16 units within a tile)
    const uint32_t a_loff = (uint32_t)(((lane & 7) + ((lane >> 3) & 1) * 8) * ASTRIDE
                                       + (lane >> 4) * 8);
    const uint32_t b_loff = (uint32_t)(((lane & 7) + (lane >> 4) * 8) * ASTRIDE
                                       + ((lane >> 3) & 1) * 8);

    constexpr int NCH = K / 32;
    issue(0, 0);
    int buf = 0;
    for (int ch = 0; ch < NCH; ch++) {
        if (ch + 1 < NCH) { issue(ch + 1, buf ^ 1); cp_wait<1>(); }
        else              { cp_wait<0>(); }
        __syncthreads();

        const uint32_t sAh = sb + (uint32_t)(buf * STAGE_U16) * 2u;
        const uint32_t sAl = sAh + TILE_U16 * 2u;
        const uint32_t sWh = sAl + TILE_U16 * 2u;
        const uint32_t sWl = sWh + TILE_U16 * 2u;

#pragma unroll
        for (int kk = 0; kk < 32; kk += 16) {
            uint32_t afh[4][4], afl[4][4];
#pragma unroll
            for (int mt = 0; mt < 4; mt++) {
                const uint32_t off = ((uint32_t)((m_base + mt * 16) * ASTRIDE + kk)
                                      + a_loff) * 2u;
                ldm_x4(afh[mt], sAh + off);
                ldm_x4(afl[mt], sAl + off);
            }
            uint32_t bfh[4][2], bfl[4][2];
#pragma unroll
            for (int np = 0; np < 2; np++) {
                const uint32_t off = ((uint32_t)((n_base + np * 16) * ASTRIDE + kk)
                                      + b_loff) * 2u;
                uint32_t th[4], tl[4];
                ldm_x4(th, sWh + off);
                ldm_x4(tl, sWl + off);
                bfh[2 * np][0] = th[0]; bfh[2 * np][1] = th[1];
                bfh[2 * np + 1][0] = th[2]; bfh[2 * np + 1][1] = th[3];
                bfl[2 * np][0] = tl[0]; bfl[2 * np][1] = tl[1];
                bfl[2 * np + 1][0] = tl[2]; bfl[2 * np + 1][1] = tl[3];
            }
#pragma unroll
            for (int mt = 0; mt < 4; mt++)
#pragma unroll
                for (int nt = 0; nt < 4; nt++) {
                    mma16816(acc[mt][nt], afh[mt], bfh[nt]);
                    mma16816(acc[mt][nt], afl[mt], bfh[nt]);
                    mma16816(acc[mt][nt], afh[mt], bfl[nt]);
                }
        }
        __syncthreads();
        buf ^= 1;
    }

    // ---- Epilogue: stage into F[n][132], coalesced col stores + BN stats ----
    float* F = (float*)smem;            // 128*132*4 = 67584 B, fits in stage area
#pragma unroll
    for (int nt = 0; nt < 4; nt++) {
        const int n = n_base + nt * 8 + 2 * (lane & 3);
        const float b0 = s_bias[n], b1 = s_bias[n + 1];
#pragma unroll
        for (int mt = 0; mt < 4; mt++) {
            const int r = m_base + mt * 16 + (lane >> 2);
            F[n * 132 + r]           = acc[mt][nt][0] + b0;
            F[(n + 1) * 132 + r]     = acc[mt][nt][1] + b1;
            F[n * 132 + r + 8]       = acc[mt][nt][2] + b0;
            F[(n + 1) * 132 + r + 8] = acc[mt][nt][3] + b1;
        }
    }
    __syncthreads();
#pragma unroll 1
    for (int c = wid; c < 128; c += 8) {
        float4 v = *(float4*)&F[c * 132 + lane * 4];
        float s = v.x + v.y + v.z + v.w;
        float q = v.x * v.x + v.y * v.y + v.z * v.z + v.w * v.w;
#pragma unroll
        for (int off = 16; off >= 1; off >>= 1) {
            s += __shfl_xor_sync(0xFFFFFFFFu, s, off);
            q += __shfl_xor_sync(0xFFFFFFFFu, q, off);
        }
        *(float4*)&Y[(size_t)(n0 + c) * MM + m0 + lane * 4] = v;
        if (lane == 0) { s_sum[c] = s; s_sq[c] = q; }
    }
    __syncthreads();
    if (tid < 128) {
        atomicAdd(&osum[n0 + tid], s_sum[tid]);
        atomicAdd(&osq[n0 + tid], s_sq[tid]);
    }
}

// ---------------------------------------------------------------------------
// Finalize BN stats -> per-channel (scale, shift)
// ---------------------------------------------------------------------------
__global__ void stats_final_kernel(const float* __restrict__ gamma,
                                   const float* __restrict__ beta,
                                   int layer) {
    const int c = threadIdx.x;
    if (c >= HH) return;
    const float invM = 1.f / (float)MM;
    const float s = g_sum[layer * 512 + c];
    const float q = g_sum[layer * 512 + 256 + c];
    const float mean = s * invM;
    const float var = fmaxf(q * invM - mean * mean, 0.f);
    const float rstd = rsqrtf(var + 1e-3f);
    const float scale = gamma[c] * rstd;
    g_nrm[layer * 512 + c] = scale;
    g_nrm[layer * 512 + 256 + c] = beta[c] - mean * scale;
}

// ---------------------------------------------------------------------------
// prep2: Y1 col-major fp32 -> BN+ReLU -> bf16 split, transposed to
// row-major [m][HH]. grid (MM/32, HH/32), block (32, 8); both sides coalesced.
// ---------------------------------------------------------------------------
__global__ __launch_bounds__(256) void prep2_kernel() {
    __shared__ float t[32][33];
    const int m0 = blockIdx.x * 32, c0 = blockIdx.y * 32;
    const int tx = threadIdx.x, ty = threadIdx.y;
#pragma unroll
    for (int i = 0; i < 4; i++) {
        const int cc = c0 + ty + 8 * i;
        float v = g_Y1[(size_t)cc * MM + m0 + tx];
        t[ty + 8 * i][tx] = fmaxf(0.f, fmaf(v, g_nrm[cc], g_nrm[256 + cc]));
    }
    __syncthreads();
#pragma unroll
    for (int i = 0; i < 4; i++) {
        const size_t m = (size_t)(m0 + ty + 8 * i);
        unsigned short h, l;
        bsplit(t[tx][ty + 8 * i], h, l);
        g_Y1h[m * HH + c0 + tx] = h;
        g_Y1l[m * HH + c0 + tx] = l;
    }
}

// ---------------------------------------------------------------------------
// Final: layer-2 BN + ReLU, Y2 col-major [c][b*4096+n] -> out[b][c][n]
// float4 both sides; grid (MM/1024, HH).
// ---------------------------------------------------------------------------
__global__ __launch_bounds__(256) void out_bn_kernel(float* __restrict__ out) {
    const int m = (blockIdx.x * 256 + threadIdx.x) * 4;
    const int c = blockIdx.y;
    float4 v = *(const float4*)&g_Y2[(size_t)c * MM + m];
    const float sc = g_nrm[512 + c], sh = g_nrm[768 + c];
    v.x = fmaxf(0.f, fmaf(v.x, sc, sh));
    v.y = fmaxf(0.f, fmaf(v.y, sc, sh));
    v.z = fmaxf(0.f, fmaf(v.z, sc, sh));
    v.w = fmaxf(0.f, fmaf(v.w, sc, sh));
    const int b = m >> 12;
    const int n = m & 4095;
    *(float4*)&out[(size_t)b * HH * NN2 + (size_t)c * NN2 + n] = v;
}

// ---------------------------------------------------------------------------
// Launch
// ---------------------------------------------------------------------------
extern "C" void kernel_launch(void* const* d_in, const int* in_sizes, int n_in,
                              void* d_out, int out_size) {
    (void)in_sizes; (void)n_in; (void)out_size;
    const float* points1   = (const float*)d_in[0];
    const float* points2   = (const float*)d_in[1];
    const float* features1 = (const float*)d_in[2];
    const float* features2 = (const float*)d_in[3];
    const float* W1  = (const float*)d_in[4];
    const float* b1  = (const float*)d_in[5];
    const float* gm1 = (const float*)d_in[6];
    const float* be1 = (const float*)d_in[7];
    const float* W2  = (const float*)d_in[8];
    const float* b2  = (const float*)d_in[9];
    const float* gm2 = (const float*)d_in[10];
    const float* be2 = (const float*)d_in[11];
    float* out = (float*)d_out;

    unsigned short *w1h, *w1l, *w2h, *w2l, *xh, *xl, *y1h, *y1l;
    float *y1, *y2, *gsum;
    cudaGetSymbolAddress((void**)&w1h, g_W1h);
    cudaGetSymbolAddress((void**)&w1l, g_W1l);
    cudaGetSymbolAddress((void**)&w2h, g_W2h);
    cudaGetSymbolAddress((void**)&w2l, g_W2l);
    cudaGetSymbolAddress((void**)&xh,  g_Xh);
    cudaGetSymbolAddress((void**)&xl,  g_Xl);
    cudaGetSymbolAddress((void**)&y1h, g_Y1h);
    cudaGetSymbolAddress((void**)&y1l, g_Y1l);
    cudaGetSymbolAddress((void**)&y1,  g_Y1);
    cudaGetSymbolAddress((void**)&y2,  g_Y2);
    cudaGetSymbolAddress((void**)&gsum, g_sum);

    cudaFuncSetAttribute(gemm_mma_kernel<CIN>,
                         cudaFuncAttributeMaxDynamicSharedMemorySize, GEMM_SMEM);
    cudaFuncSetAttribute(gemm_mma_kernel<HH>,
                         cudaFuncAttributeMaxDynamicSharedMemorySize, GEMM_SMEM);

    prep_w_kernel<<<(NW1 + NW2 + 255) / 256, 256>>>(W1, W2);
    transpose_f1_kernel<<<dim3(NN1 / 32, CC1 / 32, BB), dim3(32, 8)>>>(features1);
    concat_f2_kernel<<<dim3(NN2 / 32, CC2 / 32, BB), dim3(32, 8)>>>(features2);
    knn_scan_kernel<<<dim3(NN2 / 64, BB), 256>>>(points1, points2);
    knn_gather_kernel<<<MM / 64, 256>>>();

    gemm_mma_kernel<CIN><<<dim3(2, MM / 128), 256, GEMM_SMEM>>>(
        xh, xl, w1h, w1l, b1, y1, gsum, gsum + 256);
    stats_final_kernel<<<1, 256>>>(gm1, be1, 0);
    prep2_kernel<<<dim3(MM / 32, HH / 32), dim3(32, 8)>>>();

    gemm_mma_kernel<HH><<<dim3(2, MM / 128), 256, GEMM_SMEM>>>(
        y1h, y1l, w2h, w2l, b2, y2, gsum + 512, gsum + 768);
    stats_final_kernel<<<1, 256>>>(gm2, be2, 1);

    out_bn_kernel<<<dim3(MM / 1024, HH), 256>>>(out);
}